// round 12
// baseline (speedup 1.0000x reference)
#include <cuda_runtime.h>
#include <cuda_fp16.h>

#define N_NODES 100000
#define E_INTRA 1000000
#define E_INTER 500000
#define E_TOT   (E_INTRA + E_INTER)
#define NSEG    400000
#define NB_SCAN 391
#define SHIFT   10.0f

// ---------------- side stream for CSR/GEMM overlap (created once, pre-main) ----
struct SideStream {
    cudaStream_t s2 = nullptr;
    cudaEvent_t  e1 = nullptr, e2 = nullptr;
    bool ok = false;
    SideStream() {
        ok = (cudaStreamCreateWithFlags(&s2, cudaStreamNonBlocking) == cudaSuccess)
          && (cudaEventCreateWithFlags(&e1, cudaEventDisableTiming) == cudaSuccess)
          && (cudaEventCreateWithFlags(&e2, cudaEventDisableTiming) == cudaSuccess);
    }
};
static SideStream g_ss;

// ---------------- scratch ----------------
__device__ __half  g_h[(size_t)4 * N_NODES * 256];  // [pass][n][head*64+c] fp16
__device__ float   g_as[N_NODES * 16];
__device__ float   g_ad[N_NODES * 16];
__device__ float   g_fold[64 * 32];
__device__ float   g_bias[64];
__device__ int     g_cnt[NSEG];
__device__ int     g_off[NSEG];
__device__ int     g_cur[NSEG];
__device__ int     g_bsum[NB_SCAN];
__device__ int     g_esrc[E_TOT];

// ---------------- tf32 helpers ----------------
__device__ __forceinline__ unsigned tf32c(float f) {
    unsigned r;
    asm("cvt.rna.tf32.f32 %0, %1;" : "=r"(r) : "f"(f));
    return r;
}
__device__ __forceinline__ void mma_tf32(float* c, const unsigned* a,
                                         unsigned b0, unsigned b1) {
    asm("mma.sync.aligned.m16n8k8.row.col.f32.tf32.tf32.f32 "
        "{%0,%1,%2,%3},{%4,%5,%6,%7},{%8,%9},{%0,%1,%2,%3};"
        : "+f"(c[0]), "+f"(c[1]), "+f"(c[2]), "+f"(c[3])
        : "r"(a[0]), "r"(a[1]), "r"(a[2]), "r"(a[3]), "r"(b0), "r"(b1));
}

// ---------------- small setup kernels ----------------
__global__ void zero_k() {
    int i = blockIdx.x * blockDim.x + threadIdx.x;
    if (i < NSEG) g_cnt[i] = 0;
}

__global__ void init_out_k(float* __restrict__ out, const float* __restrict__ bi,
                           const float* __restrict__ bw) {
    int i = blockIdx.x * blockDim.x + threadIdx.x;
    if (i < N_NODES * 64) {
        int c = i & 63;
        out[i] = bi[c] + bi[64 + c] + bi[128 + c] + bw[c];
    }
}

__global__ void fold_k(const float* __restrict__ Wi, const float* __restrict__ asi,
                       const float* __restrict__ adi, const float* __restrict__ Ww,
                       const float* __restrict__ asw, const float* __restrict__ adw,
                       const float* __restrict__ bi, const float* __restrict__ bw) {
    int idx = blockIdx.x * blockDim.x + threadIdx.x;
    if (idx < 64) g_bias[idx] = bi[idx] + bi[64 + idx] + bi[128 + idx] + bw[idx];
    if (idx >= 64 * 32) return;
    int f = idx >> 5, o = idx & 31;
    int sd = o >> 4, p = (o >> 2) & 3, h = o & 3;
    const float* W = (p < 3) ? (Wi + p * 64 * 256) : Ww;
    const float* att;
    if (p < 3) att = (sd ? adi : asi) + p * 4 * 64 + h * 64;
    else       att = (sd ? adw : asw) + h * 64;
    const float* wr = W + f * 256 + h * 64;
    float s = 0.f;
    #pragma unroll 16
    for (int c = 0; c < 64; c++) s += wr[c] * att[c];
    g_fold[f * 32 + o] = s;
}

__global__ __launch_bounds__(256) void asd_k(const float* __restrict__ x) {
    __shared__ float sf[64 * 32];
    for (int i = threadIdx.x; i < 2048; i += 256) sf[i] = g_fold[i];
    __syncthreads();
    int n = blockIdx.x * blockDim.x + threadIdx.x;
    if (n >= N_NODES) return;
    float acc[32];
    #pragma unroll
    for (int o = 0; o < 32; o++) acc[o] = 0.f;
    const float4* xr = (const float4*)(x + (size_t)n * 64);
    #pragma unroll
    for (int f4 = 0; f4 < 16; f4++) {
        float4 xv = __ldg(xr + f4);
        int f = f4 * 4;
        #pragma unroll
        for (int o = 0; o < 32; o++) {
            acc[o] += xv.x * sf[(f + 0) * 32 + o] + xv.y * sf[(f + 1) * 32 + o]
                    + xv.z * sf[(f + 2) * 32 + o] + xv.w * sf[(f + 3) * 32 + o];
        }
    }
    float4* as4 = (float4*)(g_as + n * 16);
    float4* ad4 = (float4*)(g_ad + n * 16);
    #pragma unroll
    for (int q = 0; q < 4; q++) {
        as4[q] = make_float4(acc[q * 4 + 0], acc[q * 4 + 1], acc[q * 4 + 2], acc[q * 4 + 3]);
        ad4[q] = make_float4(acc[16 + q * 4 + 0], acc[16 + q * 4 + 1], acc[16 + q * 4 + 2], acc[16 + q * 4 + 3]);
    }
}

// ---------------- tensor-core GEMM (proven tf32): 128 rows, loops passes*ct ----
#define TP 68    // xs pitch (floats)
#define WP 136   // ws pitch (floats)
#define GEMM_SMEM ((128 * TP + 64 * WP) * 4)

__global__ __launch_bounds__(256, 2) void gemm_tc_k(const float* __restrict__ x,
                                                    const float* __restrict__ Wi,
                                                    const float* __restrict__ Ww) {
    extern __shared__ unsigned smem_u[];
    unsigned* xs = smem_u;                 // [128][TP] tf32
    unsigned* ws = smem_u + 128 * TP;      // [64][WP] tf32
    __half*   csm = (__half*)ws;           // C staging overlay

    int tid = threadIdx.x;
    int lane = tid & 31, wid = tid >> 5;
    int gid = lane >> 2, tig = lane & 3;
    int warp_m = wid >> 2, warp_n = wid & 3;
    int row0 = blockIdx.x * 128;

    #pragma unroll
    for (int i = 0; i < 8; i++) {
        int idx = tid + i * 256;
        int r = idx >> 4, kq = idx & 15;
        float4 v = make_float4(0.f, 0.f, 0.f, 0.f);
        if (row0 + r < N_NODES) v = *(const float4*)(x + (size_t)(row0 + r) * 64 + kq * 4);
        uint4 t;
        t.x = tf32c(v.x); t.y = tf32c(v.y); t.z = tf32c(v.z); t.w = tf32c(v.w);
        *(uint4*)(xs + r * TP + kq * 4) = t;
    }

    for (int pass = 0; pass < 4; pass++) {
        const float* W = (pass < 3) ? (Wi + pass * 64 * 256) : Ww;
        for (int ct = 0; ct < 2; ct++) {
            __syncthreads();
            #pragma unroll
            for (int i = 0; i < 8; i++) {
                int idx = tid + i * 256;
                int k = idx >> 5, cq = idx & 31;
                float4 wv = *(const float4*)(W + k * 256 + ct * 128 + cq * 4);
                uint4 t;
                t.x = tf32c(wv.x); t.y = tf32c(wv.y); t.z = tf32c(wv.z); t.w = tf32c(wv.w);
                *(uint4*)(ws + k * WP + cq * 4) = t;
            }
            __syncthreads();

            float acc[4][4][4];
            #pragma unroll
            for (int mf = 0; mf < 4; mf++)
                #pragma unroll
                for (int nf = 0; nf < 4; nf++)
                    #pragma unroll
                    for (int q = 0; q < 4; q++) acc[mf][nf][q] = 0.f;

            #pragma unroll
            for (int ks = 0; ks < 8; ks++) {
                unsigned a[4][4];
                #pragma unroll
                for (int mf = 0; mf < 4; mf++) {
                    int arow = warp_m * 64 + mf * 16 + gid;
                    int base = arow * TP + ks * 8 + tig;
                    a[mf][0] = xs[base];
                    a[mf][1] = xs[base + 8 * TP];
                    a[mf][2] = xs[base + 4];
                    a[mf][3] = xs[base + 8 * TP + 4];
                }
                #pragma unroll
                for (int nf = 0; nf < 4; nf++) {
                    int bcol = warp_n * 32 + nf * 8 + gid;
                    unsigned b0 = ws[(ks * 8 + tig) * WP + bcol];
                    unsigned b1 = ws[(ks * 8 + tig + 4) * WP + bcol];
                    #pragma unroll
                    for (int mf = 0; mf < 4; mf++)
                        mma_tf32(acc[mf][nf], a[mf], b0, b1);
                }
            }
            __syncthreads();

            #pragma unroll
            for (int mf = 0; mf < 4; mf++) {
                int r = warp_m * 64 + mf * 16 + gid;
                #pragma unroll
                for (int nf = 0; nf < 4; nf++) {
                    int c = warp_n * 32 + nf * 8 + 2 * tig;
                    __half2 lo = __floats2half2_rn(acc[mf][nf][0], acc[mf][nf][1]);
                    __half2 hi = __floats2half2_rn(acc[mf][nf][2], acc[mf][nf][3]);
                    *(__half2*)(csm + r * WP + c)       = lo;
                    *(__half2*)(csm + (r + 8) * WP + c) = hi;
                }
            }
            __syncthreads();

            #pragma unroll
            for (int i = 0; i < 8; i++) {
                int slot = tid + i * 256;
                int row = slot >> 4, q = slot & 15;
                if (row0 + row < N_NODES) {
                    *(uint4*)(g_h + ((size_t)pass * N_NODES + row0 + row) * 256 + ct * 128 + q * 8)
                        = *(const uint4*)(csm + row * WP + q * 8);
                }
            }
        }
    }
}

// ---------------- CSR build ----------------
__global__ void hist_k(const int* __restrict__ mod, const int* __restrict__ idst,
                       const int* __restrict__ wdst) {
    int e = blockIdx.x * blockDim.x + threadIdx.x;
    if (e >= E_TOT) return;
    int key;
    if (e < E_INTRA) key = __ldg(mod + e) * N_NODES + __ldg(idst + e);
    else             key = 3 * N_NODES + __ldg(wdst + e - E_INTRA);
    atomicAdd(&g_cnt[key], 1);
}

__global__ __launch_bounds__(256) void scan1_k() {
    __shared__ int sw[8];
    int b = blockIdx.x, t = threadIdx.x;
    int lane = t & 31, wid = t >> 5;
    int base = b * 1024 + t * 4;
    int v0 = (base + 0 < NSEG) ? g_cnt[base + 0] : 0;
    int v1 = (base + 1 < NSEG) ? g_cnt[base + 1] : 0;
    int v2 = (base + 2 < NSEG) ? g_cnt[base + 2] : 0;
    int v3 = (base + 3 < NSEG) ? g_cnt[base + 3] : 0;
    int tsum = v0 + v1 + v2 + v3;
    int incl = tsum;
    #pragma unroll
    for (int o = 1; o < 32; o <<= 1) {
        int n = __shfl_up_sync(0xffffffffu, incl, o);
        if (lane >= o) incl += n;
    }
    if (lane == 31) sw[wid] = incl;
    __syncthreads();
    int wbase = 0;
    for (int i = 0; i < 8; i++) if (i < wid) wbase += sw[i];
    int texcl = wbase + incl - tsum;
    if (base + 0 < NSEG) g_off[base + 0] = texcl;
    if (base + 1 < NSEG) g_off[base + 1] = texcl + v0;
    if (base + 2 < NSEG) g_off[base + 2] = texcl + v0 + v1;
    if (base + 3 < NSEG) g_off[base + 3] = texcl + v0 + v1 + v2;
    if (t == 255) g_bsum[b] = texcl + tsum;
}

__global__ __launch_bounds__(512) void scan2_k() {
    __shared__ int sw[16];
    int t = threadIdx.x, lane = t & 31, wid = t >> 5;
    int v = (t < NB_SCAN) ? g_bsum[t] : 0;
    int incl = v;
    #pragma unroll
    for (int o = 1; o < 32; o <<= 1) {
        int n = __shfl_up_sync(0xffffffffu, incl, o);
        if (lane >= o) incl += n;
    }
    if (lane == 31) sw[wid] = incl;
    __syncthreads();
    int wbase = 0;
    for (int i = 0; i < 16; i++) if (i < wid) wbase += sw[i];
    if (t < NB_SCAN) g_bsum[t] = wbase + incl - v;
}

__global__ void scan3_k() {
    int i = blockIdx.x * blockDim.x + threadIdx.x;
    if (i >= NSEG) return;
    int o = g_off[i] + g_bsum[i >> 10];
    g_off[i] = o;
    g_cur[i] = o;
}

__global__ void scat_k(const int* __restrict__ mod,
                       const int* __restrict__ isrc, const int* __restrict__ idst,
                       const int* __restrict__ wsrc, const int* __restrict__ wdst) {
    int e = blockIdx.x * blockDim.x + threadIdx.x;
    if (e >= E_TOT) return;
    int key, s;
    if (e < E_INTRA) {
        key = __ldg(mod + e) * N_NODES + __ldg(idst + e);
        s = __ldg(isrc + e);
    } else {
        key = 3 * N_NODES + __ldg(wdst + e - E_INTRA);
        s = __ldg(wsrc + e - E_INTRA);
    }
    int pos = atomicAdd(&g_cur[key], 1);
    g_esrc[pos] = s;
}

// ---------------- fused softmax + aggregate: SINGLE loop, pass-major ----------------
// out = (sum_j p_j * h_j) / denom: normalization commutes with accumulation, so
// denominator and weighted sum accumulate in ONE pass over the segment's edges.
// Every lane computes the full edge_p (broadcast loads), so each lane holds the
// complete denominator — no shfl reduction, no smem stash, no second loop.
__device__ __forceinline__ float4 edge_p(int s, float4 ad, int aoff) {
    float4 as = *(const float4*)(g_as + s * 16 + aoff);
    float v0 = as.x + ad.x; v0 = v0 > 0.f ? v0 : 0.2f * v0;
    float v1 = as.y + ad.y; v1 = v1 > 0.f ? v1 : 0.2f * v1;
    float v2 = as.z + ad.z; v2 = v2 > 0.f ? v2 : 0.2f * v2;
    float v3 = as.w + ad.w; v3 = v3 > 0.f ? v3 : 0.2f * v3;
    return make_float4(__expf(v0 - SHIFT), __expf(v1 - SHIFT),
                       __expf(v2 - SHIFT), __expf(v3 - SHIFT));
}

__global__ __launch_bounds__(128) void agg_k(float* __restrict__ out) {
    int pass = blockIdx.y;
    int w = threadIdx.x >> 5;
    int d = blockIdx.x * 4 + w;      // warp handles one dst for this pass
    int lane = threadIdx.x & 31;
    if (d >= N_NODES) return;
    int head = lane >> 3;
    int cgrp = lane & 7;
    int seg = pass * N_NODES + d;
    int off0 = g_off[seg];
    int off1 = (seg + 1 < NSEG) ? g_off[seg + 1] : E_TOT;
    int deg = off1 - off0;
    if (deg == 0) return;
    int aoff = pass * 4;

    float4 ad = *(const float4*)(g_ad + d * 16 + aoff);

    float d0 = 0.f, d1 = 0.f, d2 = 0.f, d3 = 0.f;
    float c8[8];
    #pragma unroll
    for (int q = 0; q < 8; q++) c8[q] = 0.f;
    const uint4* hbase = (const uint4*)(g_h + (size_t)pass * N_NODES * 256);

    for (int j = 0; j < deg; j++) {
        int s = g_esrc[off0 + j];                 // broadcast load
        float4 p = edge_p(s, ad, aoff);           // broadcast loads (N=1)
        d0 += p.x; d1 += p.y; d2 += p.z; d3 += p.w;
        float ph = (head == 0) ? p.x : (head == 1) ? p.y : (head == 2) ? p.z : p.w;
        uint4 v = __ldg(hbase + (size_t)s * 32 + lane);
        float2 x0 = __half22float2(*(__half2*)&v.x);
        float2 x1 = __half22float2(*(__half2*)&v.y);
        float2 x2 = __half22float2(*(__half2*)&v.z);
        float2 x3 = __half22float2(*(__half2*)&v.w);
        c8[0] += ph * x0.x; c8[1] += ph * x0.y;
        c8[2] += ph * x1.x; c8[3] += ph * x1.y;
        c8[4] += ph * x2.x; c8[5] += ph * x2.y;
        c8[6] += ph * x3.x; c8[7] += ph * x3.y;
    }

    float dh = (head == 0) ? d0 : (head == 1) ? d1 : (head == 2) ? d2 : d3;
    float ih = 0.25f / fmaxf(dh, 1e-16f);
    #pragma unroll
    for (int q = 0; q < 8; q++) c8[q] *= ih;

    // head-reduce within warp: lanes {cgrp+8k} hold same col ranges
    #pragma unroll
    for (int q = 0; q < 8; q++) {
        c8[q] += __shfl_xor_sync(0xffffffffu, c8[q], 8);
        c8[q] += __shfl_xor_sync(0xffffffffu, c8[q], 16);
    }
    int cbase = cgrp * 8 + head * 2;
    atomicAdd(out + (size_t)d * 64 + cbase,     c8[head * 2]);
    atomicAdd(out + (size_t)d * 64 + cbase + 1, c8[head * 2 + 1]);
}

// ---------------- launch ----------------
extern "C" void kernel_launch(void* const* d_in, const int* in_sizes, int n_in,
                              void* d_out, int out_size) {
    const float* x        = (const float*)d_in[0];
    const int*   modality = (const int*)d_in[1];
    const int*   isrc     = (const int*)d_in[2];
    const int*   idst     = (const int*)d_in[3];
    const int*   wsrc     = (const int*)d_in[4];
    const int*   wdst     = (const int*)d_in[5];
    const float* W_intra  = (const float*)d_in[6];
    const float* as_i     = (const float*)d_in[7];
    const float* ad_i     = (const float*)d_in[8];
    const float* b_i      = (const float*)d_in[9];
    const float* W_inter  = (const float*)d_in[10];
    const float* as_w     = (const float*)d_in[11];
    const float* ad_w     = (const float*)d_in[12];
    const float* b_w      = (const float*)d_in[13];
    float* out = (float*)d_out;

    cudaFuncSetAttribute(gemm_tc_k, cudaFuncAttributeMaxDynamicSharedMemorySize, GEMM_SMEM);

    if (g_ss.ok) {
        // fork: CSR-build + out-init chain on s2, projection chain on main stream
        cudaEventRecord(g_ss.e1, 0);
        cudaStreamWaitEvent(g_ss.s2, g_ss.e1, 0);

        zero_k<<<(NSEG + 255) / 256, 256, 0, g_ss.s2>>>();                         // 1
        fold_k<<<8, 256>>>(W_intra, as_i, ad_i, W_inter, as_w, ad_w, b_i, b_w);    // 2
        asd_k<<<(N_NODES + 255) / 256, 256>>>(x);                                  // 3
        gemm_tc_k<<<(N_NODES + 127) / 128, 256, GEMM_SMEM>>>(x, W_intra, W_inter); // 4 (profiled)
        init_out_k<<<(N_NODES * 64 + 255) / 256, 256, 0, g_ss.s2>>>(out, b_i, b_w);
        hist_k<<<(E_TOT + 255) / 256, 256, 0, g_ss.s2>>>(modality, idst, wdst);
        scan1_k<<<NB_SCAN, 256, 0, g_ss.s2>>>();
        scan2_k<<<1, 512, 0, g_ss.s2>>>();
        scan3_k<<<(NSEG + 255) / 256, 256, 0, g_ss.s2>>>();
        scat_k<<<(E_TOT + 255) / 256, 256, 0, g_ss.s2>>>(modality, isrc, idst, wsrc, wdst);
        cudaEventRecord(g_ss.e2, g_ss.s2);
        cudaStreamWaitEvent(0, g_ss.e2, 0);

        agg_k<<<dim3((N_NODES + 3) / 4, 4), 128>>>(out);
    } else {
        // sequential fallback
        zero_k<<<(NSEG + 255) / 256, 256>>>();
        fold_k<<<8, 256>>>(W_intra, as_i, ad_i, W_inter, as_w, ad_w, b_i, b_w);
        asd_k<<<(N_NODES + 255) / 256, 256>>>(x);
        gemm_tc_k<<<(N_NODES + 127) / 128, 256, GEMM_SMEM>>>(x, W_intra, W_inter);
        init_out_k<<<(N_NODES * 64 + 255) / 256, 256>>>(out, b_i, b_w);
        hist_k<<<(E_TOT + 255) / 256, 256>>>(modality, idst, wdst);
        scan1_k<<<NB_SCAN, 256>>>();
        scan2_k<<<1, 512>>>();
        scan3_k<<<(NSEG + 255) / 256, 256>>>();
        scat_k<<<(E_TOT + 255) / 256, 256>>>(modality, isrc, idst, wsrc, wdst);
        agg_k<<<dim3((N_NODES + 3) / 4, 4), 128>>>(out);
    }
}

// round 13
// speedup vs baseline: 1.3620x; 1.3620x over previous
#include <cuda_runtime.h>
#include <cuda_fp16.h>

#define N_NODES 100000
#define E_INTRA 1000000
#define E_INTER 500000
#define E_TOT   (E_INTRA + E_INTER)
#define NSEG    400000
#define NB_SCAN 391
#define SHIFT   10.0f

// ---------------- side stream (created once, pre-main) ----------------
struct SideStream {
    cudaStream_t s2 = nullptr;
    cudaEvent_t  e1 = nullptr, e2 = nullptr;
    bool ok = false;
    SideStream() {
        ok = (cudaStreamCreateWithFlags(&s2, cudaStreamNonBlocking) == cudaSuccess)
          && (cudaEventCreateWithFlags(&e1, cudaEventDisableTiming) == cudaSuccess)
          && (cudaEventCreateWithFlags(&e2, cudaEventDisableTiming) == cudaSuccess);
    }
};
static SideStream g_ss;

// ---------------- scratch ----------------
__device__ __half  g_y[(size_t)N_NODES * 1024];   // [n][p*256+h*64+c] fp16, 205MB
__device__ __half  g_wcat[64 * 1024];             // [o][p*256+h*64+c] fp16 (pre-transposed, /4)
__device__ float   g_as[N_NODES * 16];
__device__ float   g_ad[N_NODES * 16];
__device__ float   g_fold[64 * 32];
__device__ float   g_bias[64];
__device__ int     g_cnt[NSEG];
__device__ int     g_off[NSEG];
__device__ int     g_cur[NSEG];
__device__ int     g_bsum[NB_SCAN];
__device__ int     g_esrc[E_TOT];

// ---------------- fp16 mma helper (known-correct from R10) ----------------
__device__ __forceinline__ void mma_f16(float* c, const unsigned* a,
                                        unsigned b0, unsigned b1) {
    asm("mma.sync.aligned.m16n8k16.row.col.f32.f16.f16.f32 "
        "{%0,%1,%2,%3},{%4,%5,%6,%7},{%8,%9},{%0,%1,%2,%3};"
        : "+f"(c[0]), "+f"(c[1]), "+f"(c[2]), "+f"(c[3])
        : "r"(a[0]), "r"(a[1]), "r"(a[2]), "r"(a[3]), "r"(b0), "r"(b1));
}

// ---------------- small setup kernels ----------------
__global__ void zero_k() {
    int i = blockIdx.x * blockDim.x + threadIdx.x;
    if (i < NSEG) g_cnt[i] = 0;
}

// Wcat[o][k], k=(p,h,c): W_p[c, h*64+o] * 0.25  (head-avg folded in)
__global__ void wcat_k(const float* __restrict__ Wi, const float* __restrict__ Ww) {
    int idx = blockIdx.x * blockDim.x + threadIdx.x;
    if (idx >= 64 * 1024) return;
    int o = idx >> 10, k = idx & 1023;
    int p = k >> 8, h = (k >> 6) & 3, c = k & 63;
    float v = (p < 3) ? Wi[p * 16384 + c * 256 + h * 64 + o]
                      : Ww[c * 256 + h * 64 + o];
    g_wcat[idx] = __float2half_rn(0.25f * v);
}

__global__ void fold_k(const float* __restrict__ Wi, const float* __restrict__ asi,
                       const float* __restrict__ adi, const float* __restrict__ Ww,
                       const float* __restrict__ asw, const float* __restrict__ adw,
                       const float* __restrict__ bi, const float* __restrict__ bw) {
    int idx = blockIdx.x * blockDim.x + threadIdx.x;
    if (idx < 64) g_bias[idx] = bi[idx] + bi[64 + idx] + bi[128 + idx] + bw[idx];
    if (idx >= 64 * 32) return;
    int f = idx >> 5, o = idx & 31;
    int sd = o >> 4, p = (o >> 2) & 3, h = o & 3;
    const float* W = (p < 3) ? (Wi + p * 64 * 256) : Ww;
    const float* att;
    if (p < 3) att = (sd ? adi : asi) + p * 4 * 64 + h * 64;
    else       att = (sd ? adw : asw) + h * 64;
    const float* wr = W + f * 256 + h * 64;
    float s = 0.f;
    #pragma unroll 16
    for (int c = 0; c < 64; c++) s += wr[c] * att[c];
    g_fold[f * 32 + o] = s;
}

__global__ __launch_bounds__(256) void asd_k(const float* __restrict__ x) {
    __shared__ float sf[64 * 32];
    for (int i = threadIdx.x; i < 2048; i += 256) sf[i] = g_fold[i];
    __syncthreads();
    int n = blockIdx.x * blockDim.x + threadIdx.x;
    if (n >= N_NODES) return;
    float acc[32];
    #pragma unroll
    for (int o = 0; o < 32; o++) acc[o] = 0.f;
    const float4* xr = (const float4*)(x + (size_t)n * 64);
    #pragma unroll
    for (int f4 = 0; f4 < 16; f4++) {
        float4 xv = __ldg(xr + f4);
        int f = f4 * 4;
        #pragma unroll
        for (int o = 0; o < 32; o++) {
            acc[o] += xv.x * sf[(f + 0) * 32 + o] + xv.y * sf[(f + 1) * 32 + o]
                    + xv.z * sf[(f + 2) * 32 + o] + xv.w * sf[(f + 3) * 32 + o];
        }
    }
    float4* as4 = (float4*)(g_as + n * 16);
    float4* ad4 = (float4*)(g_ad + n * 16);
    #pragma unroll
    for (int q = 0; q < 4; q++) {
        as4[q] = make_float4(acc[q * 4 + 0], acc[q * 4 + 1], acc[q * 4 + 2], acc[q * 4 + 3]);
        ad4[q] = make_float4(acc[16 + q * 4 + 0], acc[16 + q * 4 + 1], acc[16 + q * 4 + 2], acc[16 + q * 4 + 3]);
    }
}

// ---------------- CSR build ----------------
__global__ void hist_k(const int* __restrict__ mod, const int* __restrict__ idst,
                       const int* __restrict__ wdst) {
    int e = blockIdx.x * blockDim.x + threadIdx.x;
    if (e >= E_TOT) return;
    int key;
    if (e < E_INTRA) key = __ldg(mod + e) * N_NODES + __ldg(idst + e);
    else             key = 3 * N_NODES + __ldg(wdst + e - E_INTRA);
    atomicAdd(&g_cnt[key], 1);
}

__global__ __launch_bounds__(256) void scan1_k() {
    __shared__ int sw[8];
    int b = blockIdx.x, t = threadIdx.x;
    int lane = t & 31, wid = t >> 5;
    int base = b * 1024 + t * 4;
    int v0 = (base + 0 < NSEG) ? g_cnt[base + 0] : 0;
    int v1 = (base + 1 < NSEG) ? g_cnt[base + 1] : 0;
    int v2 = (base + 2 < NSEG) ? g_cnt[base + 2] : 0;
    int v3 = (base + 3 < NSEG) ? g_cnt[base + 3] : 0;
    int tsum = v0 + v1 + v2 + v3;
    int incl = tsum;
    #pragma unroll
    for (int o = 1; o < 32; o <<= 1) {
        int n = __shfl_up_sync(0xffffffffu, incl, o);
        if (lane >= o) incl += n;
    }
    if (lane == 31) sw[wid] = incl;
    __syncthreads();
    int wbase = 0;
    for (int i = 0; i < 8; i++) if (i < wid) wbase += sw[i];
    int texcl = wbase + incl - tsum;
    if (base + 0 < NSEG) g_off[base + 0] = texcl;
    if (base + 1 < NSEG) g_off[base + 1] = texcl + v0;
    if (base + 2 < NSEG) g_off[base + 2] = texcl + v0 + v1;
    if (base + 3 < NSEG) g_off[base + 3] = texcl + v0 + v1 + v2;
    if (t == 255) g_bsum[b] = texcl + tsum;
}

__global__ __launch_bounds__(512) void scan2_k() {
    __shared__ int sw[16];
    int t = threadIdx.x, lane = t & 31, wid = t >> 5;
    int v = (t < NB_SCAN) ? g_bsum[t] : 0;
    int incl = v;
    #pragma unroll
    for (int o = 1; o < 32; o <<= 1) {
        int n = __shfl_up_sync(0xffffffffu, incl, o);
        if (lane >= o) incl += n;
    }
    if (lane == 31) sw[wid] = incl;
    __syncthreads();
    int wbase = 0;
    for (int i = 0; i < 16; i++) if (i < wid) wbase += sw[i];
    if (t < NB_SCAN) g_bsum[t] = wbase + incl - v;
}

__global__ void scan3_k() {
    int i = blockIdx.x * blockDim.x + threadIdx.x;
    if (i >= NSEG) return;
    int o = g_off[i] + g_bsum[i >> 10];
    g_off[i] = o;
    g_cur[i] = o;
}

__global__ void scat_k(const int* __restrict__ mod,
                       const int* __restrict__ isrc, const int* __restrict__ idst,
                       const int* __restrict__ wsrc, const int* __restrict__ wdst) {
    int e = blockIdx.x * blockDim.x + threadIdx.x;
    if (e >= E_TOT) return;
    int key, s;
    if (e < E_INTRA) {
        key = __ldg(mod + e) * N_NODES + __ldg(idst + e);
        s = __ldg(isrc + e);
    } else {
        key = 3 * N_NODES + __ldg(wdst + e - E_INTRA);
        s = __ldg(wsrc + e - E_INTRA);
    }
    int pos = atomicAdd(&g_cur[key], 1);
    g_esrc[pos] = s;
}

// ---------------- x-space softmax aggregation: Y[d, pass, h, :] ----------------
// Two-phase per warp (R11-proven shape): phase A computes all edge p's in one
// lane-parallel sweep (stash in smem); phase B serially accumulates 8B x-loads
// (L2-resident 25.6MB working set). Y = (Σ p_h·x)/denom stored fp16 directly.
__device__ __forceinline__ float4 edge_p(int s, float4 ad, int aoff) {
    float4 as = *(const float4*)(g_as + s * 16 + aoff);
    float v0 = as.x + ad.x; v0 = v0 > 0.f ? v0 : 0.2f * v0;
    float v1 = as.y + ad.y; v1 = v1 > 0.f ? v1 : 0.2f * v1;
    float v2 = as.z + ad.z; v2 = v2 > 0.f ? v2 : 0.2f * v2;
    float v3 = as.w + ad.w; v3 = v3 > 0.f ? v3 : 0.2f * v3;
    return make_float4(__expf(v0 - SHIFT), __expf(v1 - SHIFT),
                       __expf(v2 - SHIFT), __expf(v3 - SHIFT));
}

__global__ __launch_bounds__(128) void aggx_k(const float* __restrict__ x) {
    __shared__ float4 pbuf[4][32];
    __shared__ int    sbuf[4][32];
    int pass = blockIdx.y;
    int w = threadIdx.x >> 5;
    int d = blockIdx.x * 4 + w;      // grid exact: d < N_NODES
    int lane = threadIdx.x & 31;
    int seg = pass * N_NODES + d;
    int off0 = g_off[seg];
    int off1 = (seg + 1 < NSEG) ? g_off[seg + 1] : E_TOT;
    int deg = off1 - off0;
    int aoff = pass * 4;
    __half2* yrow = (__half2*)(g_y + (size_t)d * 1024 + pass * 256);

    if (deg == 0) {
        __half2 z = __floats2half2_rn(0.f, 0.f);
        #pragma unroll
        for (int h = 0; h < 4; h++) yrow[h * 32 + lane] = z;
        return;
    }

    float4 ad = *(const float4*)(g_ad + d * 16 + aoff);

    // phase A: lane-parallel edge logits; stash (p, s) for first 32 edges
    float d0 = 0.f, d1 = 0.f, d2 = 0.f, d3 = 0.f;
    for (int j = lane; j < deg; j += 32) {
        int s = g_esrc[off0 + j];
        float4 p = edge_p(s, ad, aoff);
        if (j < 32) { pbuf[w][j] = p; sbuf[w][j] = s; }
        d0 += p.x; d1 += p.y; d2 += p.z; d3 += p.w;
    }
    #pragma unroll
    for (int o = 16; o > 0; o >>= 1) {
        d0 += __shfl_xor_sync(0xffffffffu, d0, o);
        d1 += __shfl_xor_sync(0xffffffffu, d1, o);
        d2 += __shfl_xor_sync(0xffffffffu, d2, o);
        d3 += __shfl_xor_sync(0xffffffffu, d3, o);
    }
    __syncwarp();
    float i0 = 1.f / fmaxf(d0, 1e-16f);   // NOTE: 0.25 folded into Wcat
    float i1 = 1.f / fmaxf(d1, 1e-16f);
    float i2 = 1.f / fmaxf(d2, 1e-16f);
    float i3 = 1.f / fmaxf(d3, 1e-16f);

    // phase B: lane covers x cols 2*lane, 2*lane+1
    float c00 = 0.f, c01 = 0.f, c10 = 0.f, c11 = 0.f;
    float c20 = 0.f, c21 = 0.f, c30 = 0.f, c31 = 0.f;
    for (int j = 0; j < deg; j++) {
        int s; float4 p;
        if (j < 32) { s = sbuf[w][j]; p = pbuf[w][j]; }
        else        { s = g_esrc[off0 + j]; p = edge_p(s, ad, aoff); }
        float2 xv = *(const float2*)(x + (size_t)s * 64 + 2 * lane);
        c00 += p.x * xv.x; c01 += p.x * xv.y;
        c10 += p.y * xv.x; c11 += p.y * xv.y;
        c20 += p.z * xv.x; c21 += p.z * xv.y;
        c30 += p.w * xv.x; c31 += p.w * xv.y;
    }
    yrow[0 * 32 + lane] = __floats2half2_rn(c00 * i0, c01 * i0);
    yrow[1 * 32 + lane] = __floats2half2_rn(c10 * i1, c11 * i1);
    yrow[2 * 32 + lane] = __floats2half2_rn(c20 * i2, c21 * i2);
    yrow[3 * 32 + lane] = __floats2half2_rn(c30 * i3, c31 * i3);
}

// ---------------- final GEMM: out[N,64] = Y[N,1024] @ Wcat^T + bias ----------------
// fp16 mma m16n8k16. A = Y rows (row-major k), B = g_wcat [o][k] (pre-transposed).
// Fragment addressing identical to R10's verified-correct mainloop.
#define YP2 68                      // smem pitch in half2 (A and B)
#define CPF 68                      // csm pitch in floats
#define XS_BYTES (128 * YP2 * 4)
#define WS_BYTES (64 * YP2 * 4)
#define CS_BYTES (128 * CPF * 4)
#define GEMMY_SMEM (XS_BYTES + WS_BYTES + CS_BYTES + 256)

__global__ __launch_bounds__(256, 2) void gemmy_k(float* __restrict__ out) {
    extern __shared__ char smem_c[];
    __half2* xs  = (__half2*)smem_c;                       // [128][YP2]
    __half2* ws  = (__half2*)(smem_c + XS_BYTES);          // [64][YP2]
    float*   csm = (float*)(smem_c + XS_BYTES + WS_BYTES); // [128][CPF]
    float*   sb  = (float*)(smem_c + XS_BYTES + WS_BYTES + CS_BYTES); // bias[64]

    int tid = threadIdx.x;
    int lane = tid & 31, wid = tid >> 5;
    int gid = lane >> 2, tig = lane & 3;
    int warp_m = wid >> 1, warp_n = wid & 1;   // 4 x 2 warp grid
    int row0 = blockIdx.x * 128;
    if (tid < 64) sb[tid] = g_bias[tid];

    float acc[2][4][4];
    #pragma unroll
    for (int mf = 0; mf < 2; mf++)
        #pragma unroll
        for (int nf = 0; nf < 4; nf++)
            #pragma unroll
            for (int q = 0; q < 4; q++) acc[mf][nf][q] = 0.f;

    for (int ch = 0; ch < 8; ch++) {           // K = 1024 in 8 chunks of 128
        int kc0 = ch * 128;                    // in halfs
        __syncthreads();
        // load A chunk [128 rows][128 k] fp16
        #pragma unroll
        for (int i = 0; i < 8; i++) {
            int slot = tid + i * 256;
            int r = slot >> 4, q = slot & 15;
            uint4 v = make_uint4(0u, 0u, 0u, 0u);
            int row = row0 + r;
            if (row < N_NODES)
                v = *(const uint4*)(g_y + (size_t)row * 1024 + kc0 + q * 8);
            *(uint4*)&xs[r * YP2 + q * 4] = v;
        }
        // load B chunk [64 o][128 k] fp16 (already transposed in global)
        #pragma unroll
        for (int i = 0; i < 4; i++) {
            int slot = tid + i * 256;
            int o = slot >> 4, q = slot & 15;
            *(uint4*)&ws[o * YP2 + q * 4] =
                *(const uint4*)(g_wcat + o * 1024 + kc0 + q * 8);
        }
        __syncthreads();

        #pragma unroll
        for (int ks = 0; ks < 8; ks++) {       // 128 k = 8 x k16
            int kc = ks * 8;                   // half2 units
            unsigned a[2][4];
            #pragma unroll
            for (int mf = 0; mf < 2; mf++) {
                int arow = warp_m * 32 + mf * 16 + gid;
                a[mf][0] = *(unsigned*)&xs[arow * YP2 + kc + tig];
                a[mf][1] = *(unsigned*)&xs[(arow + 8) * YP2 + kc + tig];
                a[mf][2] = *(unsigned*)&xs[arow * YP2 + kc + tig + 4];
                a[mf][3] = *(unsigned*)&xs[(arow + 8) * YP2 + kc + tig + 4];
            }
            #pragma unroll
            for (int nf = 0; nf < 4; nf++) {
                int ncol = warp_n * 32 + nf * 8 + gid;
                unsigned b0 = *(unsigned*)&ws[ncol * YP2 + kc + tig];
                unsigned b1 = *(unsigned*)&ws[ncol * YP2 + kc + tig + 4];
                #pragma unroll
                for (int mf = 0; mf < 2; mf++)
                    mma_f16(acc[mf][nf], a[mf], b0, b1);
            }
        }
    }
    __syncthreads();

    // stage C (fp32) then coalesced biased store
    #pragma unroll
    for (int mf = 0; mf < 2; mf++) {
        int r = warp_m * 32 + mf * 16 + gid;
        #pragma unroll
        for (int nf = 0; nf < 4; nf++) {
            int c = warp_n * 32 + nf * 8 + 2 * tig;
            *(float2*)&csm[r * CPF + c]       = make_float2(acc[mf][nf][0], acc[mf][nf][1]);
            *(float2*)&csm[(r + 8) * CPF + c] = make_float2(acc[mf][nf][2], acc[mf][nf][3]);
        }
    }
    __syncthreads();

    #pragma unroll
    for (int i = 0; i < 8; i++) {
        int slot = tid + i * 256;
        int row = slot >> 4, q = slot & 15;
        if (row0 + row < N_NODES) {
            float4 v;
            v.x = csm[row * CPF + q * 4 + 0] + sb[q * 4 + 0];
            v.y = csm[row * CPF + q * 4 + 1] + sb[q * 4 + 1];
            v.z = csm[row * CPF + q * 4 + 2] + sb[q * 4 + 2];
            v.w = csm[row * CPF + q * 4 + 3] + sb[q * 4 + 3];
            *(float4*)(out + (size_t)(row0 + row) * 64 + q * 4) = v;
        }
    }
}

// ---------------- launch ----------------
extern "C" void kernel_launch(void* const* d_in, const int* in_sizes, int n_in,
                              void* d_out, int out_size) {
    const float* x        = (const float*)d_in[0];
    const int*   modality = (const int*)d_in[1];
    const int*   isrc     = (const int*)d_in[2];
    const int*   idst     = (const int*)d_in[3];
    const int*   wsrc     = (const int*)d_in[4];
    const int*   wdst     = (const int*)d_in[5];
    const float* W_intra  = (const float*)d_in[6];
    const float* as_i     = (const float*)d_in[7];
    const float* ad_i     = (const float*)d_in[8];
    const float* b_i      = (const float*)d_in[9];
    const float* W_inter  = (const float*)d_in[10];
    const float* as_w     = (const float*)d_in[11];
    const float* ad_w     = (const float*)d_in[12];
    const float* b_w      = (const float*)d_in[13];
    float* out = (float*)d_out;

    cudaFuncSetAttribute(gemmy_k, cudaFuncAttributeMaxDynamicSharedMemorySize, GEMMY_SMEM);

    if (g_ss.ok) {
        cudaEventRecord(g_ss.e1, 0);
        cudaStreamWaitEvent(g_ss.s2, g_ss.e1, 0);

        // s2: CSR build + Wcat (independent of x-chain)
        zero_k<<<(NSEG + 255) / 256, 256, 0, g_ss.s2>>>();
        wcat_k<<<(64 * 1024 + 255) / 256, 256, 0, g_ss.s2>>>(W_intra, W_inter);
        hist_k<<<(E_TOT + 255) / 256, 256, 0, g_ss.s2>>>(modality, idst, wdst);
        scan1_k<<<NB_SCAN, 256, 0, g_ss.s2>>>();
        scan2_k<<<1, 512, 0, g_ss.s2>>>();
        scan3_k<<<(NSEG + 255) / 256, 256, 0, g_ss.s2>>>();
        scat_k<<<(E_TOT + 255) / 256, 256, 0, g_ss.s2>>>(modality, isrc, idst, wsrc, wdst);
        cudaEventRecord(g_ss.e2, g_ss.s2);

        // main: logits chain, then join, then aggregate + GEMM
        fold_k<<<8, 256>>>(W_intra, as_i, ad_i, W_inter, as_w, ad_w, b_i, b_w);
        asd_k<<<(N_NODES + 255) / 256, 256>>>(x);
        cudaStreamWaitEvent(0, g_ss.e2, 0);
        aggx_k<<<dim3(N_NODES / 4, 4), 128>>>(x);
        gemmy_k<<<(N_NODES + 127) / 128, 256, GEMMY_SMEM>>>(out);
    } else {
        zero_k<<<(NSEG + 255) / 256, 256>>>();
        wcat_k<<<(64 * 1024 + 255) / 256, 256>>>(W_intra, W_inter);
        fold_k<<<8, 256>>>(W_intra, as_i, ad_i, W_inter, as_w, ad_w, b_i, b_w);
        asd_k<<<(N_NODES + 255) / 256, 256>>>(x);
        hist_k<<<(E_TOT + 255) / 256, 256>>>(modality, idst, wdst);
        scan1_k<<<NB_SCAN, 256>>>();
        scan2_k<<<1, 512>>>();
        scan3_k<<<(NSEG + 255) / 256, 256>>>();
        scat_k<<<(E_TOT + 255) / 256, 256>>>(modality, isrc, idst, wsrc, wdst);
        aggx_k<<<dim3(N_NODES / 4, 4), 128>>>(x);
        gemmy_k<<<(N_NODES + 127) / 128, 256, GEMMY_SMEM>>>(out);
    }
}